// round 11
// baseline (speedup 1.0000x reference)
#include <cuda_runtime.h>
#include <math.h>
#include <float.h>

// Problem constants
#define B_    2
#define S_    2048
#define BS_   4096
#define V_    50257
#define V4_   50260          // V_ padded to multiple of 4 (row stride for tables)
#define N_    512
#define NM1_  511
#define NZ2_  16
#define CH2_  (BS_/NZ2_)     // 256 samples per z-slice
#define WPB_T 8              // warps (tokens) per block in k_tables

#define SCORE_OFF  ((size_t)BS_ * (size_t)V_)
#define MEANDT_OFF (SCORE_OFF + (size_t)BS_ * (size_t)S_)

// ----------------------------- device scratch -----------------------------
__device__ float g_rv[BS_];
__device__ float g_k1[BS_];
__device__ float g_tgt[BS_];
__device__ float g_r[BS_];
__device__ float g_c[BS_];
__device__ int   g_list[BS_];
__device__ int   g_krank[BS_];
__device__ int   g_done = 0;

// metadata, swizzled layout: slot(j) = (j%16)*32 + j/16  (j = sorted position)
__device__ __align__(16) float4 g_meta4[N_];   // (sw, sb, ss, rank-as-int-bits) per slot
__device__ __align__(16) int    g_perm[N_];    // slot -> original w_out column (perm(j)+1, 0=dummy)

__device__ __align__(16) float g_A [(size_t)N_ * V4_];   // suffix tables at used ranks
__device__ __align__(16) float g_D [(size_t)N_ * V4_];   // D' = suffB - suffC
__device__ __align__(16) float g_E [V4_];                // totalC + b_out
__device__ __align__(16) float g_W0[V4_];                // w_out[:,0]

// ----------------------------- helpers -----------------------------
__device__ __forceinline__ float blockReduceSum(float v, float* sh) {
    #pragma unroll
    for (int o = 16; o > 0; o >>= 1) v += __shfl_down_sync(0xffffffffu, v, o);
    int lane = threadIdx.x & 31;
    int w    = threadIdx.x >> 5;
    if (lane == 0) sh[w] = v;
    __syncthreads();
    if (w == 0) {
        v = (lane < (int)(blockDim.x >> 5)) ? sh[lane] : 0.f;
        #pragma unroll
        for (int o = 16; o > 0; o >>= 1) v += __shfl_down_sync(0xffffffffu, v, o);
        if (lane == 0) sh[0] = v;
    }
    __syncthreads();
    float r = sh[0];
    __syncthreads();
    return r;
}

__device__ __forceinline__ float clipf(float x, float lo, float hi) {
    return fminf(fmaxf(x, lo), hi);
}

// ----------------------------- K0: step1 (embed in-block + score1 stats + k1) --------------------
__global__ void __launch_bounds__(512) k_step1(const int* __restrict__ x,
                                               const float* __restrict__ dt,
                                               const float* __restrict__ r0) {
    __shared__ float srow[S_];
    __shared__ float sred[32];
    int gid = blockIdx.x;
    int b = gid >> 11;
    int i = gid & (S_ - 1);
    int tid = threadIdx.x;

    #pragma unroll
    for (int q = 0; q < 4; q++) {
        int j = q * 512 + tid;
        float r = r0[x[b * S_ + j]];
        srow[j] = r / fmaxf(fabsf(r), 1e-12f);
    }
    __syncthreads();
    float ri = srow[i];

    float s1 = 0.f, s2 = 0.f;
    #pragma unroll
    for (int q = 0; q < 4; q++) {
        float d = fabsf(ri - srow[q * 512 + tid]);
        s1 += d;
        s2 += d * d;
    }
    s1 = blockReduceSum(s1, sred);
    s2 = blockReduceSum(s2, sred);

    float mean = s1 * (1.f / (float)S_);
    float ssq  = fmaxf(s2 - s1 * mean, 0.f);
    float var  = ssq * (1.f / (float)(S_ - 1));
    float thr  = fmaxf(mean + 2.f * sqrtf(var), 1e-12f);
    float inv  = 1.f / thr;

    float acc = 0.f;
    for (int j = tid; j < i; j += 512) {
        float d = fabsf(ri - srow[j]);
        if (d <= thr) acc += (1.f - d * inv) * srow[j];
    }
    acc = blockReduceSum(acc, sred);

    if (tid == 0) {
        float dtc = clipf(dt[b], 0.f, 1.f);
        float k1  = clipf(dtc * acc, -1.f, 1.f);
        g_rv[gid]  = ri;
        g_k1[gid]  = k1;
        g_tgt[gid] = ri + k1;
    }
}

// ----------------------------- K1: step2 + last-block (sort + bucket) ----------------------------
// Sort sentinels: real breakpoints in (0,1); "never clips" = 2.0; dummy slot 511 = 3.0
// (unique max -> pinned at sorted position 511 under strict comparisons).
__global__ void __launch_bounds__(512) k_step2(const float* __restrict__ dt,
                                               const float* __restrict__ w_diff,
                                               const float* __restrict__ b_diff,
                                               float* __restrict__ out,
                                               int write_score, size_t out_size) {
    __shared__ float srow[S_];
    __shared__ float sred[32];
    __shared__ int   sdone;
    int gid = blockIdx.x;
    int b = gid >> 11;
    int i = gid & (S_ - 1);
    int tid = threadIdx.x;

    for (int j = tid; j < S_; j += 512) srow[j] = g_tgt[b * S_ + j];
    __syncthreads();
    float ti = srow[i];

    float s1 = 0.f, s2 = 0.f;
    #pragma unroll
    for (int q = 0; q < 4; q++) {
        float d = fabsf(ti - srow[q * 512 + tid]);
        s1 += d;
        s2 += d * d;
    }
    s1 = blockReduceSum(s1, sred);
    s2 = blockReduceSum(s2, sred);

    float mean = s1 * (1.f / (float)S_);
    float ssq  = fmaxf(s2 - s1 * mean, 0.f);
    float var  = ssq * (1.f / (float)(S_ - 1));
    float thr  = fmaxf(mean + 2.f * sqrtf(var), 1e-12f);
    float inv  = 1.f / thr;

    float acc = 0.f, accs = 0.f;
    size_t rowoff = SCORE_OFF + (size_t)gid * S_;
    #pragma unroll
    for (int q = 0; q < 4; q++) {
        int j = q * 512 + tid;
        float d  = fabsf(ti - srow[j]);
        float sc = (j < i && d <= thr) ? (1.f - d * inv) : 0.f;
        if (write_score) __stcs(out + rowoff + j, sc);
        acc  += sc * srow[j];
        accs += sc;
    }
    acc  = blockReduceSum(acc, sred);
    accs = blockReduceSum(accs, sred);

    if (tid == 0) {
        float dtc = clipf(dt[b], 0.f, 1.f);
        float k2  = clipf(dtc * acc, -1.f, 1.f);
        float z   = g_rv[gid] + 0.5f * (g_k1[gid] + k2);
        g_r[gid]  = z / fmaxf(fabsf(z), 1e-12f);
        g_c[gid]  = clipf(accs * (1.f / (float)S_), 0.f, 1.f);
    }

    // ---- last-block-done: the final block runs sort + bucket ----
    __threadfence();
    if (tid == 0) {
        int old = atomicAdd(&g_done, 1);
        sdone = (old == (int)gridDim.x - 1) ? 1 : 0;
        if (sdone) g_done = 0;                 // reset for next graph replay
    }
    __syncthreads();
    if (!sdone) return;

    // ===== sort stage =====
    __shared__ float skey[N_];
    __shared__ int   sval[N_];
    __shared__ float ssw[N_], ssb[N_], sss[N_];   // by swizzled slot

    float tkey = 3.0f;
    if (tid < NM1_) {
        float w = w_diff[tid], bb = b_diff[tid];
        tkey = 2.0f;
        if (w > 0.f && (w + bb) > 1.f)        tkey = (1.f - bb) / w;
        else if (w < 0.f && (w + bb) < -1.f)  tkey = (-1.f - bb) / w;
    }
    skey[tid] = tkey;
    sval[tid] = tid;
    __syncthreads();

    for (int ksz = 2; ksz <= N_; ksz <<= 1) {
        for (int jsz = ksz >> 1; jsz > 0; jsz >>= 1) {
            int ixj = tid ^ jsz;
            if (ixj > tid) {
                bool up = ((tid & ksz) == 0);
                float a = skey[tid], c = skey[ixj];
                bool sw = up ? (a > c) : (a < c);
                if (sw) {
                    skey[tid] = c; skey[ixj] = a;
                    int tmp = sval[tid]; sval[tid] = sval[ixj]; sval[ixj] = tmp;
                }
            }
            __syncthreads();
        }
    }

    int n = sval[tid];
    float key = skey[tid];
    int slot = ((tid & 15) << 5) | (tid >> 4);
    if (n < NM1_) {
        float w = w_diff[n], bb = b_diff[n];
        ssw[slot] = w;
        ssb[slot] = bb;
        sss[slot] = (key >= 2.0f) ? 0.f : (w > 0.f ? 1.f : -1.f);
        g_perm[slot] = n + 1;
    } else {
        ssw[slot] = 0.f; ssb[slot] = 0.f; sss[slot] = 0.f;
        g_perm[slot] = 0;
    }

    if (tid == 0 && out_size > MEANDT_OFF) {
        float d0 = clipf(dt[0], 0.f, 1.f);
        float d1 = clipf(dt[1], 0.f, 1.f);
        out[MEANDT_OFF] = 0.5f * (d0 + d1);
    }

    // ===== bucket stage (kidx + parallel scan + rank + scatter) =====
    __shared__ int bs1[N_];
    __shared__ int bs2[N_];
    __shared__ int posA[N_];
    __shared__ int rnkS[N_];

    bs1[tid] = 0;
    __syncthreads();

    int kx[BS_ / 512];
    #pragma unroll
    for (int q = 0; q < BS_ / 512; q++) {
        int sid = q * 512 + tid;
        float c = g_c[sid];
        int lo = 0, hi = N_;
        while (lo < hi) {
            int mid = (lo + hi) >> 1;
            if (skey[mid] <= c) lo = mid + 1; else hi = mid;
        }
        kx[q] = lo;                  // provably <= 511 (sentinel keys 2.0/3.0 > 1 >= c)
        atomicAdd(&bs1[lo], 1);
    }
    __syncthreads();

    int myc = bs1[tid];
    int myf = (myc > 0) ? 1 : 0;
    bs2[tid] = myf;
    __syncthreads();

    for (int off = 1; off < N_; off <<= 1) {
        int a = 0, bb2 = 0;
        if (tid >= off) { a = bs1[tid - off]; bb2 = bs2[tid - off]; }
        __syncthreads();
        bs1[tid] += a; bs2[tid] += bb2;
        __syncthreads();
    }

    posA[tid] = bs1[tid] - myc;
    int r = myf ? (bs2[tid] - 1) : -1;
    rnkS[tid] = r;
    g_meta4[slot] = make_float4(ssw[slot], ssb[slot], sss[slot], __int_as_float(r));
    __syncthreads();

    #pragma unroll
    for (int q = 0; q < BS_ / 512; q++) {
        int sid = q * 512 + tid;
        int p = atomicAdd(&posA[kx[q]], 1);
        g_list[p] = sid;
        g_krank[sid] = rnkS[kx[q]];
    }
}

// ----------------------------- K2: tables from w_out rows (gather form, R8-proven) ---------------
// One warp per token t. Lane l owns sorted positions j = l*16 + i; slot m = i*32 + l.
// Row stored densely; passes gather row[sperm[m]] + read packed metadata (LDS.128).
__global__ void __launch_bounds__(256) k_tables(const float* __restrict__ w_out,
                                                const float* __restrict__ b_out) {
    __shared__ float4 smeta[N_];          // 8 KB
    __shared__ int    sperm[N_];          // 2 KB
    __shared__ float  srow[WPB_T][N_];    // 16 KB

    int tid = threadIdx.x;
    for (int j = tid; j < N_; j += 256) {
        smeta[j] = g_meta4[j];
        sperm[j] = g_perm[j];
    }

    int wid  = tid >> 5;
    int lane = tid & 31;
    int t = blockIdx.x * WPB_T + wid;
    bool tv = (t < V_);

    if (tv) {
        const float4* rp = (const float4*)(w_out + (size_t)t * N_);
        float4* sp = (float4*)srow[wid];
        #pragma unroll
        for (int q = 0; q < 4; q++) sp[q * 32 + lane] = rp[q * 32 + lane];
    }
    __syncthreads();
    if (!tv) return;

    const float* row = srow[wid];

    // pass 1: per-lane suffix totals over its 16 positions
    float ta = 0.f, tb = 0.f, tc = 0.f;
    #pragma unroll
    for (int i = 15; i >= 0; i--) {
        int m = i * 32 + lane;
        float  w  = row[sperm[m]];
        float4 md = smeta[m];
        ta = fmaf(w, md.x, ta);
        tb = fmaf(w, md.y, tb);
        tc = fmaf(w, md.z, tc);
    }

    // inclusive suffix scan across lanes (lane l gets sum over lanes >= l)
    float ia = ta, ib = tb, ic = tc;
    #pragma unroll
    for (int off = 1; off < 32; off <<= 1) {
        float xa = __shfl_down_sync(0xffffffffu, ia, off);
        float xb = __shfl_down_sync(0xffffffffu, ib, off);
        float xc = __shfl_down_sync(0xffffffffu, ic, off);
        if (lane + off < 32) { ia += xa; ib += xb; ic += xc; }
    }
    float ba = ia - ta;
    float bb = ib - tb;
    float bc = ic - tc;
    float totc = __shfl_sync(0xffffffffu, ic, 0);

    // pass 2: walk down, emit at used ranks
    float aa = ba, ab = bb, ac = bc;
    #pragma unroll
    for (int i = 15; i >= 0; i--) {
        int m = i * 32 + lane;
        float  w  = row[sperm[m]];
        float4 md = smeta[m];
        aa = fmaf(w, md.x, aa);
        ab = fmaf(w, md.y, ab);
        ac = fmaf(w, md.z, ac);
        int rk = __float_as_int(md.w);
        if (rk >= 0) {
            g_A[(size_t)rk * V4_ + t] = aa;
            g_D[(size_t)rk * V4_ + t] = ab - ac;
        }
    }

    if (lane == 0) {
        g_W0[t] = row[0];          // column 0 = w_out[:,0] (row stored unpermuted)
        g_E[t]  = totc + b_out[t];
    }
}

// ----------------------------- K3: logits (run-prefetch, 512 thr x 2 tokens) --------------------
__global__ void __launch_bounds__(512) k_logits(float* __restrict__ out) {
    __shared__ int   slist[CH2_];
    __shared__ int   srk[CH2_];
    __shared__ float sr[CH2_];
    __shared__ float sc[CH2_];
    __shared__ int   sflag[CH2_];
    __shared__ int   srunstart[CH2_ + 1];
    __shared__ int   srunrank[CH2_];
    __shared__ int   snruns;

    int tid = threadIdx.x;
    if (tid < CH2_) {
        int sid = g_list[blockIdx.y * CH2_ + tid];
        slist[tid] = sid;
        srk[tid]   = g_krank[sid];
        sr[tid]    = g_r[sid];
        sc[tid]    = g_c[sid];
    }
    __syncthreads();

    // run detection (list is sorted by rank within the slice)
    if (tid < CH2_)
        sflag[tid] = (tid == 0 || srk[tid] != srk[tid - 1]) ? 1 : 0;
    __syncthreads();
    for (int off = 1; off < CH2_; off <<= 1) {
        int v2 = 0;
        if (tid < CH2_ && tid >= off) v2 = sflag[tid - off];
        __syncthreads();
        if (tid < CH2_) sflag[tid] += v2;
        __syncthreads();
    }
    if (tid < CH2_) {
        bool isStart = (tid == 0) || (srk[tid] != srk[tid - 1]);
        if (isStart) {
            int rid = sflag[tid] - 1;
            srunstart[rid] = tid;
            srunrank[rid]  = srk[tid];
        }
    }
    if (tid == CH2_ - 1) {
        snruns = sflag[tid];
        srunstart[sflag[tid]] = CH2_;
    }
    __syncthreads();

    int t0 = blockIdx.x * 1024 + tid;        // tokens t0 and t0+512
    int t1 = t0 + 512;
    bool v0 = (t0 < V_), v1 = (t1 < V_);
    int l0 = (t0 < V4_) ? t0 : (V4_ - 1);
    int l1 = (t1 < V4_) ? t1 : (V4_ - 1);
    float w00 = g_W0[l0], w01 = g_W0[l1];
    float E0  = g_E[l0],  E1  = g_E[l1];

    int nruns = snruns;
    {
        size_t ro = (size_t)srunrank[0] * V4_;
        float A0 = g_A[ro + l0], A1 = g_A[ro + l1];
        float D0 = g_D[ro + l0] + E0, D1 = g_D[ro + l1] + E1;
        float An0 = 0.f, An1 = 0.f, Dn0 = 0.f, Dn1 = 0.f;

        for (int rid = 0; rid < nruns; rid++) {
            int p1 = srunstart[rid + 1];
            if (rid + 1 < nruns) {
                size_t rn = (size_t)srunrank[rid + 1] * V4_;
                An0 = g_A[rn + l0]; An1 = g_A[rn + l1];
                Dn0 = g_D[rn + l0] + E0; Dn1 = g_D[rn + l1] + E1;
            }
            for (int p = srunstart[rid]; p < p1; p++) {
                float r = sr[p], c = sc[p];
                size_t base = (size_t)slist[p] * V_;
                float x0 = fmaf(r, w00, fmaf(c, A0, D0));
                float x1 = fmaf(r, w01, fmaf(c, A1, D1));
                x0 = fminf(fmaxf(x0, -2.f), 2.f);
                x1 = fminf(fmaxf(x1, -2.f), 2.f);
                if (v0) __stcs(out + base + t0, x0);
                if (v1) __stcs(out + base + t1, x1);
            }
            A0 = An0; A1 = An1; D0 = Dn0; D1 = Dn1;
        }
    }
}

// ----------------------------- launch -----------------------------
extern "C" void kernel_launch(void* const* d_in, const int* in_sizes, int n_in,
                              void* d_out, int out_size) {
    const int*   x      = (const int*)  d_in[0];
    const float* dt     = (const float*)d_in[1];
    const float* r0     = (const float*)d_in[2];
    const float* w_diff = (const float*)d_in[3];
    const float* b_diff = (const float*)d_in[4];
    const float* w_out  = (const float*)d_in[5];
    const float* b_out  = (const float*)d_in[6];
    float* out = (float*)d_out;
    size_t osz = (size_t)out_size;

    int write_score = (osz >= SCORE_OFF + (size_t)BS_ * S_) ? 1 : 0;

    k_step1<<<BS_, 512>>>(x, dt, r0);
    k_step2<<<BS_, 512>>>(dt, w_diff, b_diff, out, write_score, osz);
    k_tables<<<(V_ + WPB_T - 1) / WPB_T, 256>>>(w_out, b_out);

    dim3 lg((V4_ + 1023) / 1024, NZ2_);
    k_logits<<<lg, 512>>>(out);
}

// round 13
// speedup vs baseline: 1.1189x; 1.1189x over previous
#include <cuda_runtime.h>
#include <math.h>
#include <float.h>

// Problem constants
#define B_    2
#define S_    2048
#define BS_   4096
#define V_    50257
#define V4_   50260          // V_ padded to multiple of 4 (row stride for tables)
#define N_    512
#define NM1_  511
#define NZ2_  16
#define CH2_  (BS_/NZ2_)     // 256 samples per z-slice
#define WPB_T 8              // warps (tokens) per block in k_tables

#define SCORE_OFF  ((size_t)BS_ * (size_t)V_)
#define MEANDT_OFF (SCORE_OFF + (size_t)BS_ * (size_t)S_)

// ----------------------------- device scratch -----------------------------
__device__ float g_rv[BS_];
__device__ float g_k1[BS_];
__device__ float g_tgt[BS_];
__device__ float g_r[BS_];
__device__ float g_c[BS_];
__device__ int   g_list[BS_];
__device__ int   g_krank[BS_];
__device__ int   g_done = 0;

// metadata, swizzled layout: slot(j) = (j%16)*32 + j/16  (j = sorted position)
__device__ __align__(16) float4 g_meta4[N_];   // (sw, sb, ss, rank-as-int-bits) per slot
__device__ __align__(16) int    g_perm[N_];    // slot -> original w_out column (perm(j)+1, 0=dummy)

__device__ __align__(16) float g_A [(size_t)N_ * V4_];   // suffix tables at used ranks
__device__ __align__(16) float g_D [(size_t)N_ * V4_];   // FINAL D (E folded in at build time)
__device__ __align__(16) float g_W0[V4_];                // w_out[:,0]

// ----------------------------- helpers -----------------------------
__device__ __forceinline__ float blockReduceSum(float v, float* sh) {
    #pragma unroll
    for (int o = 16; o > 0; o >>= 1) v += __shfl_down_sync(0xffffffffu, v, o);
    int lane = threadIdx.x & 31;
    int w    = threadIdx.x >> 5;
    if (lane == 0) sh[w] = v;
    __syncthreads();
    if (w == 0) {
        v = (lane < (int)(blockDim.x >> 5)) ? sh[lane] : 0.f;
        #pragma unroll
        for (int o = 16; o > 0; o >>= 1) v += __shfl_down_sync(0xffffffffu, v, o);
        if (lane == 0) sh[0] = v;
    }
    __syncthreads();
    float r = sh[0];
    __syncthreads();
    return r;
}

__device__ __forceinline__ float clipf(float x, float lo, float hi) {
    return fminf(fmaxf(x, lo), hi);
}

// ----------------------------- K0: step1 (embed in-block + score1 stats + k1) --------------------
__global__ void __launch_bounds__(512) k_step1(const int* __restrict__ x,
                                               const float* __restrict__ dt,
                                               const float* __restrict__ r0) {
    __shared__ float srow[S_];
    __shared__ float sred[32];
    int gid = blockIdx.x;
    int b = gid >> 11;
    int i = gid & (S_ - 1);
    int tid = threadIdx.x;

    #pragma unroll
    for (int q = 0; q < 4; q++) {
        int j = q * 512 + tid;
        float r = r0[x[b * S_ + j]];
        srow[j] = r / fmaxf(fabsf(r), 1e-12f);
    }
    __syncthreads();
    float ri = srow[i];

    float s1 = 0.f, s2 = 0.f;
    #pragma unroll
    for (int q = 0; q < 4; q++) {
        float d = fabsf(ri - srow[q * 512 + tid]);
        s1 += d;
        s2 += d * d;
    }
    s1 = blockReduceSum(s1, sred);
    s2 = blockReduceSum(s2, sred);

    float mean = s1 * (1.f / (float)S_);
    float ssq  = fmaxf(s2 - s1 * mean, 0.f);
    float var  = ssq * (1.f / (float)(S_ - 1));
    float thr  = fmaxf(mean + 2.f * sqrtf(var), 1e-12f);
    float inv  = 1.f / thr;

    float acc = 0.f;
    for (int j = tid; j < i; j += 512) {
        float d = fabsf(ri - srow[j]);
        if (d <= thr) acc += (1.f - d * inv) * srow[j];
    }
    acc = blockReduceSum(acc, sred);

    if (tid == 0) {
        float dtc = clipf(dt[b], 0.f, 1.f);
        float k1  = clipf(dtc * acc, -1.f, 1.f);
        g_rv[gid]  = ri;
        g_k1[gid]  = k1;
        g_tgt[gid] = ri + k1;
    }
}

// ----------------------------- K1: step2 + last-block (sort + bucket) ----------------------------
// Sort sentinels: real breakpoints in (0,1); "never clips" = 2.0; dummy slot 511 = 3.0
// (unique max -> pinned at sorted position 511 under strict comparisons).
__global__ void __launch_bounds__(512) k_step2(const float* __restrict__ dt,
                                               const float* __restrict__ w_diff,
                                               const float* __restrict__ b_diff,
                                               float* __restrict__ out,
                                               int write_score, size_t out_size) {
    __shared__ float srow[S_];
    __shared__ float sred[32];
    __shared__ int   sdone;
    int gid = blockIdx.x;
    int b = gid >> 11;
    int i = gid & (S_ - 1);
    int tid = threadIdx.x;

    for (int j = tid; j < S_; j += 512) srow[j] = g_tgt[b * S_ + j];
    __syncthreads();
    float ti = srow[i];

    float s1 = 0.f, s2 = 0.f;
    #pragma unroll
    for (int q = 0; q < 4; q++) {
        float d = fabsf(ti - srow[q * 512 + tid]);
        s1 += d;
        s2 += d * d;
    }
    s1 = blockReduceSum(s1, sred);
    s2 = blockReduceSum(s2, sred);

    float mean = s1 * (1.f / (float)S_);
    float ssq  = fmaxf(s2 - s1 * mean, 0.f);
    float var  = ssq * (1.f / (float)(S_ - 1));
    float thr  = fmaxf(mean + 2.f * sqrtf(var), 1e-12f);
    float inv  = 1.f / thr;

    float acc = 0.f, accs = 0.f;
    size_t rowoff = SCORE_OFF + (size_t)gid * S_;
    #pragma unroll
    for (int q = 0; q < 4; q++) {
        int j = q * 512 + tid;
        float d  = fabsf(ti - srow[j]);
        float sc = (j < i && d <= thr) ? (1.f - d * inv) : 0.f;
        if (write_score) __stcs(out + rowoff + j, sc);
        acc  += sc * srow[j];
        accs += sc;
    }
    acc  = blockReduceSum(acc, sred);
    accs = blockReduceSum(accs, sred);

    if (tid == 0) {
        float dtc = clipf(dt[b], 0.f, 1.f);
        float k2  = clipf(dtc * acc, -1.f, 1.f);
        float z   = g_rv[gid] + 0.5f * (g_k1[gid] + k2);
        g_r[gid]  = z / fmaxf(fabsf(z), 1e-12f);
        g_c[gid]  = clipf(accs * (1.f / (float)S_), 0.f, 1.f);
    }

    // ---- last-block-done: the final block runs sort + bucket ----
    __threadfence();
    if (tid == 0) {
        int old = atomicAdd(&g_done, 1);
        sdone = (old == (int)gridDim.x - 1) ? 1 : 0;
        if (sdone) g_done = 0;                 // reset for next graph replay
    }
    __syncthreads();
    if (!sdone) return;

    // ===== sort stage =====
    __shared__ float skey[N_];
    __shared__ int   sval[N_];
    __shared__ float ssw[N_], ssb[N_], sss[N_];   // by swizzled slot

    float tkey = 3.0f;
    if (tid < NM1_) {
        float w = w_diff[tid], bb = b_diff[tid];
        tkey = 2.0f;
        if (w > 0.f && (w + bb) > 1.f)        tkey = (1.f - bb) / w;
        else if (w < 0.f && (w + bb) < -1.f)  tkey = (-1.f - bb) / w;
    }
    skey[tid] = tkey;
    sval[tid] = tid;
    __syncthreads();

    for (int ksz = 2; ksz <= N_; ksz <<= 1) {
        for (int jsz = ksz >> 1; jsz > 0; jsz >>= 1) {
            int ixj = tid ^ jsz;
            if (ixj > tid) {
                bool up = ((tid & ksz) == 0);
                float a = skey[tid], c = skey[ixj];
                bool sw = up ? (a > c) : (a < c);
                if (sw) {
                    skey[tid] = c; skey[ixj] = a;
                    int tmp = sval[tid]; sval[tid] = sval[ixj]; sval[ixj] = tmp;
                }
            }
            __syncthreads();
        }
    }

    int n = sval[tid];
    float key = skey[tid];
    int slot = ((tid & 15) << 5) | (tid >> 4);
    if (n < NM1_) {
        float w = w_diff[n], bb = b_diff[n];
        ssw[slot] = w;
        ssb[slot] = bb;
        sss[slot] = (key >= 2.0f) ? 0.f : (w > 0.f ? 1.f : -1.f);
        g_perm[slot] = n + 1;
    } else {
        ssw[slot] = 0.f; ssb[slot] = 0.f; sss[slot] = 0.f;
        g_perm[slot] = 0;
    }

    if (tid == 0 && out_size > MEANDT_OFF) {
        float d0 = clipf(dt[0], 0.f, 1.f);
        float d1 = clipf(dt[1], 0.f, 1.f);
        out[MEANDT_OFF] = 0.5f * (d0 + d1);
    }

    // ===== bucket stage (kidx + parallel scan + rank + scatter) =====
    __shared__ int bs1[N_];
    __shared__ int bs2[N_];
    __shared__ int posA[N_];
    __shared__ int rnkS[N_];

    bs1[tid] = 0;
    __syncthreads();

    int kx[BS_ / 512];
    #pragma unroll
    for (int q = 0; q < BS_ / 512; q++) {
        int sid = q * 512 + tid;
        float c = g_c[sid];
        int lo = 0, hi = N_;
        while (lo < hi) {
            int mid = (lo + hi) >> 1;
            if (skey[mid] <= c) lo = mid + 1; else hi = mid;
        }
        kx[q] = lo;                  // provably <= 511 (sentinel keys 2.0/3.0 > 1 >= c)
        atomicAdd(&bs1[lo], 1);
    }
    __syncthreads();

    int myc = bs1[tid];
    int myf = (myc > 0) ? 1 : 0;
    bs2[tid] = myf;
    __syncthreads();

    for (int off = 1; off < N_; off <<= 1) {
        int a = 0, bb2 = 0;
        if (tid >= off) { a = bs1[tid - off]; bb2 = bs2[tid - off]; }
        __syncthreads();
        bs1[tid] += a; bs2[tid] += bb2;
        __syncthreads();
    }

    posA[tid] = bs1[tid] - myc;
    int r = myf ? (bs2[tid] - 1) : -1;
    rnkS[tid] = r;
    g_meta4[slot] = make_float4(ssw[slot], ssb[slot], sss[slot], __int_as_float(r));
    __syncthreads();

    #pragma unroll
    for (int q = 0; q < BS_ / 512; q++) {
        int sid = q * 512 + tid;
        int p = atomicAdd(&posA[kx[q]], 1);
        g_list[p] = sid;
        g_krank[sid] = rnkS[kx[q]];
    }
}

// ----------------------------- K2: tables from w_out rows (gather form) --------------------------
// One warp per token t. Lane l owns sorted positions j = l*16 + i; slot m = i*32 + l.
// D table holds the FINAL D (= D' + totc + b_out), so k_logits needs no E.
__global__ void __launch_bounds__(256) k_tables(const float* __restrict__ w_out,
                                                const float* __restrict__ b_out) {
    __shared__ float4 smeta[N_];          // 8 KB
    __shared__ int    sperm[N_];          // 2 KB
    __shared__ float  srow[WPB_T][N_];    // 16 KB

    int tid = threadIdx.x;
    for (int j = tid; j < N_; j += 256) {
        smeta[j] = g_meta4[j];
        sperm[j] = g_perm[j];
    }

    int wid  = tid >> 5;
    int lane = tid & 31;
    int t = blockIdx.x * WPB_T + wid;
    bool tv = (t < V_);

    if (tv) {
        const float4* rp = (const float4*)(w_out + (size_t)t * N_);
        float4* sp = (float4*)srow[wid];
        #pragma unroll
        for (int q = 0; q < 4; q++) sp[q * 32 + lane] = rp[q * 32 + lane];
    }
    __syncthreads();
    if (!tv) return;

    const float* row = srow[wid];
    float bo = b_out[t];

    // pass 1: per-lane suffix totals over its 16 positions
    float ta = 0.f, tb = 0.f, tc = 0.f;
    #pragma unroll
    for (int i = 15; i >= 0; i--) {
        int m = i * 32 + lane;
        float  w  = row[sperm[m]];
        float4 md = smeta[m];
        ta = fmaf(w, md.x, ta);
        tb = fmaf(w, md.y, tb);
        tc = fmaf(w, md.z, tc);
    }

    // inclusive suffix scan across lanes (lane l gets sum over lanes >= l)
    float ia = ta, ib = tb, ic = tc;
    #pragma unroll
    for (int off = 1; off < 32; off <<= 1) {
        float xa = __shfl_down_sync(0xffffffffu, ia, off);
        float xb = __shfl_down_sync(0xffffffffu, ib, off);
        float xc = __shfl_down_sync(0xffffffffu, ic, off);
        if (lane + off < 32) { ia += xa; ib += xb; ic += xc; }
    }
    float ba = ia - ta;
    float bb = ib - tb;
    float bc = ic - tc;
    float totc = __shfl_sync(0xffffffffu, ic, 0);
    float dadd = totc + bo;

    // pass 2: walk down, emit at used ranks (final D)
    float aa = ba, ab = bb, ac = bc;
    #pragma unroll
    for (int i = 15; i >= 0; i--) {
        int m = i * 32 + lane;
        float  w  = row[sperm[m]];
        float4 md = smeta[m];
        aa = fmaf(w, md.x, aa);
        ab = fmaf(w, md.y, ab);
        ac = fmaf(w, md.z, ac);
        int rk = __float_as_int(md.w);
        if (rk >= 0) {
            g_A[(size_t)rk * V4_ + t] = aa;
            g_D[(size_t)rk * V4_ + t] = ab - ac + dadd;
        }
    }

    if (lane == 0) g_W0[t] = row[0];
}

// ----------------------------- K3: logits (4 tok/thread, STG.64 parity-aligned) ------------------
// Thread t0 writes tokens t0+par .. t0+par+3 (par = sample-row parity); token t0 for
// par=1 samples is covered by the preceding thread, EXCEPT global token 0, which the
// t0==0 thread writes explicitly.
__global__ void __launch_bounds__(512) k_logits(float* __restrict__ out) {
    __shared__ float4 sm[CH2_];   // (r, c, base-as-int-bits, rank-as-int-bits)

    int tid = threadIdx.x;
    if (tid < CH2_) {
        int sid = g_list[blockIdx.y * CH2_ + tid];
        sm[tid] = make_float4(g_r[sid], g_c[sid],
                              __int_as_float(sid * V_),
                              __int_as_float(g_krank[sid]));
    }
    __syncthreads();

    int t0 = blockIdx.x * 2048 + tid * 4;       // multiple of 4 (even)
    if (t0 >= V_) return;
    bool full  = (t0 + 4 < V_);                 // all stored tokens valid
    bool left0 = (t0 == 0);                     // global left edge

    int lt[5];
    float w0[5];
    #pragma unroll
    for (int j = 0; j < 5; j++) {
        int q = t0 + j; if (q > V4_ - 1) q = V4_ - 1;
        lt[j] = q;
        w0[j] = g_W0[q];
    }

    int kcur = -1;
    float A[5], D[5];
    #pragma unroll
    for (int j = 0; j < 5; j++) { A[j] = 0.f; D[j] = 0.f; }

    for (int p = 0; p < CH2_; p++) {
        float4 md = sm[p];
        int rk = __float_as_int(md.w);
        if (rk != kcur) {
            size_t ro = (size_t)rk * V4_;
            #pragma unroll
            for (int j = 0; j < 5; j++) {
                A[j] = g_A[ro + lt[j]];
                D[j] = g_D[ro + lt[j]];
            }
            kcur = rk;
        }
        float r = md.x, c = md.y;
        int base = __float_as_int(md.z);
        int par  = base & 1;                 // parity shift -> 8B-aligned stores

        float x0, x1, x2, x3;
        if (par) {
            x0 = fmaf(r, w0[1], fmaf(c, A[1], D[1]));
            x1 = fmaf(r, w0[2], fmaf(c, A[2], D[2]));
            x2 = fmaf(r, w0[3], fmaf(c, A[3], D[3]));
            x3 = fmaf(r, w0[4], fmaf(c, A[4], D[4]));
        } else {
            x0 = fmaf(r, w0[0], fmaf(c, A[0], D[0]));
            x1 = fmaf(r, w0[1], fmaf(c, A[1], D[1]));
            x2 = fmaf(r, w0[2], fmaf(c, A[2], D[2]));
            x3 = fmaf(r, w0[3], fmaf(c, A[3], D[3]));
        }
        x0 = fminf(fmaxf(x0, -2.f), 2.f);
        x1 = fminf(fmaxf(x1, -2.f), 2.f);
        x2 = fminf(fmaxf(x2, -2.f), 2.f);
        x3 = fminf(fmaxf(x3, -2.f), 2.f);

        float* addr = out + (size_t)(unsigned)base + (t0 + par);
        if (full) {
            __stcs((float2*)addr,       make_float2(x0, x1));
            __stcs((float2*)(addr + 2), make_float2(x2, x3));
        } else {
            int ts = t0 + par;
            if (ts     < V_) __stcs(addr,     x0);
            if (ts + 1 < V_) __stcs(addr + 1, x1);
            if (ts + 2 < V_) __stcs(addr + 2, x2);
            if (ts + 3 < V_) __stcs(addr + 3, x3);
        }
        // left-edge patch: token 0 for odd-base samples has no predecessor thread
        if (left0 && par) {
            float xz = fmaf(r, w0[0], fmaf(c, A[0], D[0]));
            xz = fminf(fmaxf(xz, -2.f), 2.f);
            __stcs(out + (size_t)(unsigned)base, xz);
        }
    }
}

// ----------------------------- launch -----------------------------
extern "C" void kernel_launch(void* const* d_in, const int* in_sizes, int n_in,
                              void* d_out, int out_size) {
    const int*   x      = (const int*)  d_in[0];
    const float* dt     = (const float*)d_in[1];
    const float* r0     = (const float*)d_in[2];
    const float* w_diff = (const float*)d_in[3];
    const float* b_diff = (const float*)d_in[4];
    const float* w_out  = (const float*)d_in[5];
    const float* b_out  = (const float*)d_in[6];
    float* out = (float*)d_out;
    size_t osz = (size_t)out_size;

    int write_score = (osz >= SCORE_OFF + (size_t)BS_ * S_) ? 1 : 0;

    k_step1<<<BS_, 512>>>(x, dt, r0);
    k_step2<<<BS_, 512>>>(dt, w_diff, b_diff, out, write_score, osz);
    k_tables<<<(V_ + WPB_T - 1) / WPB_T, 256>>>(w_out, b_out);

    dim3 lg((V4_ + 2047) / 2048, NZ2_);
    k_logits<<<lg, 512>>>(out);
}

// round 14
// speedup vs baseline: 1.2406x; 1.1087x over previous
#include <cuda_runtime.h>
#include <math.h>
#include <float.h>

// Problem constants
#define B_    2
#define S_    2048
#define BS_   4096
#define V_    50257
#define VP_   50264          // table row stride: multiple of 8, >= V_+7 (pad for float4 window loads)
#define N_    512
#define NM1_  511
#define NZ2_  16
#define CH2_  (BS_/NZ2_)     // 256 samples per z-slice
#define WPB_T 8              // warps (tokens) per block in k_tables

#define SCORE_OFF  ((size_t)BS_ * (size_t)V_)
#define MEANDT_OFF (SCORE_OFF + (size_t)BS_ * (size_t)S_)

// ----------------------------- device scratch -----------------------------
__device__ float g_rv[BS_];
__device__ float g_k1[BS_];
__device__ float g_tgt[BS_];
__device__ float g_r[BS_];
__device__ float g_c[BS_];
__device__ int   g_list[BS_];
__device__ int   g_krank[BS_];
__device__ int   g_done = 0;

// metadata, swizzled layout: slot(j) = (j%16)*32 + j/16  (j = sorted position)
__device__ __align__(16) float4 g_meta4[N_];   // (sw, sb, ss, rank-as-int-bits) per slot
__device__ __align__(16) int    g_perm[N_];    // slot -> original w_out column (perm(j)+1, 0=dummy)

__device__ __align__(16) float g_A [(size_t)N_ * VP_];   // suffix tables at used ranks
__device__ __align__(16) float g_D [(size_t)N_ * VP_];   // FINAL D (E folded in at build time)
__device__ __align__(16) float g_W0[VP_];                // w_out[:,0]

// ----------------------------- helpers -----------------------------
__device__ __forceinline__ float blockReduceSum(float v, float* sh) {
    #pragma unroll
    for (int o = 16; o > 0; o >>= 1) v += __shfl_down_sync(0xffffffffu, v, o);
    int lane = threadIdx.x & 31;
    int w    = threadIdx.x >> 5;
    if (lane == 0) sh[w] = v;
    __syncthreads();
    if (w == 0) {
        v = (lane < (int)(blockDim.x >> 5)) ? sh[lane] : 0.f;
        #pragma unroll
        for (int o = 16; o > 0; o >>= 1) v += __shfl_down_sync(0xffffffffu, v, o);
        if (lane == 0) sh[0] = v;
    }
    __syncthreads();
    float r = sh[0];
    __syncthreads();
    return r;
}

__device__ __forceinline__ float clipf(float x, float lo, float hi) {
    return fminf(fmaxf(x, lo), hi);
}

// ----------------------------- K0: step1 (embed in-block + score1 stats + k1) --------------------
__global__ void __launch_bounds__(512) k_step1(const int* __restrict__ x,
                                               const float* __restrict__ dt,
                                               const float* __restrict__ r0) {
    __shared__ float srow[S_];
    __shared__ float sred[32];
    int gid = blockIdx.x;
    int b = gid >> 11;
    int i = gid & (S_ - 1);
    int tid = threadIdx.x;

    #pragma unroll
    for (int q = 0; q < 4; q++) {
        int j = q * 512 + tid;
        float r = r0[x[b * S_ + j]];
        srow[j] = r / fmaxf(fabsf(r), 1e-12f);
    }
    __syncthreads();
    float ri = srow[i];

    float s1 = 0.f, s2 = 0.f;
    #pragma unroll
    for (int q = 0; q < 4; q++) {
        float d = fabsf(ri - srow[q * 512 + tid]);
        s1 += d;
        s2 += d * d;
    }
    s1 = blockReduceSum(s1, sred);
    s2 = blockReduceSum(s2, sred);

    float mean = s1 * (1.f / (float)S_);
    float ssq  = fmaxf(s2 - s1 * mean, 0.f);
    float var  = ssq * (1.f / (float)(S_ - 1));
    float thr  = fmaxf(mean + 2.f * sqrtf(var), 1e-12f);
    float inv  = 1.f / thr;

    float acc = 0.f;
    for (int j = tid; j < i; j += 512) {
        float d = fabsf(ri - srow[j]);
        if (d <= thr) acc += (1.f - d * inv) * srow[j];
    }
    acc = blockReduceSum(acc, sred);

    if (tid == 0) {
        float dtc = clipf(dt[b], 0.f, 1.f);
        float k1  = clipf(dtc * acc, -1.f, 1.f);
        g_rv[gid]  = ri;
        g_k1[gid]  = k1;
        g_tgt[gid] = ri + k1;
    }
}

// ----------------------------- K1: step2 + last-block (sort + bucket) ----------------------------
// Sort sentinels: real breakpoints in (0,1); "never clips" = 2.0; dummy slot 511 = 3.0
// (unique max -> pinned at sorted position 511 under strict comparisons).
__global__ void __launch_bounds__(512) k_step2(const float* __restrict__ dt,
                                               const float* __restrict__ w_diff,
                                               const float* __restrict__ b_diff,
                                               float* __restrict__ out,
                                               int write_score, size_t out_size) {
    __shared__ float srow[S_];
    __shared__ float sred[32];
    __shared__ int   sdone;
    int gid = blockIdx.x;
    int b = gid >> 11;
    int i = gid & (S_ - 1);
    int tid = threadIdx.x;

    for (int j = tid; j < S_; j += 512) srow[j] = g_tgt[b * S_ + j];
    __syncthreads();
    float ti = srow[i];

    float s1 = 0.f, s2 = 0.f;
    #pragma unroll
    for (int q = 0; q < 4; q++) {
        float d = fabsf(ti - srow[q * 512 + tid]);
        s1 += d;
        s2 += d * d;
    }
    s1 = blockReduceSum(s1, sred);
    s2 = blockReduceSum(s2, sred);

    float mean = s1 * (1.f / (float)S_);
    float ssq  = fmaxf(s2 - s1 * mean, 0.f);
    float var  = ssq * (1.f / (float)(S_ - 1));
    float thr  = fmaxf(mean + 2.f * sqrtf(var), 1e-12f);
    float inv  = 1.f / thr;

    float acc = 0.f, accs = 0.f;
    size_t rowoff = SCORE_OFF + (size_t)gid * S_;
    #pragma unroll
    for (int q = 0; q < 4; q++) {
        int j = q * 512 + tid;
        float d  = fabsf(ti - srow[j]);
        float sc = (j < i && d <= thr) ? (1.f - d * inv) : 0.f;
        if (write_score) __stcs(out + rowoff + j, sc);
        acc  += sc * srow[j];
        accs += sc;
    }
    acc  = blockReduceSum(acc, sred);
    accs = blockReduceSum(accs, sred);

    if (tid == 0) {
        float dtc = clipf(dt[b], 0.f, 1.f);
        float k2  = clipf(dtc * acc, -1.f, 1.f);
        float z   = g_rv[gid] + 0.5f * (g_k1[gid] + k2);
        g_r[gid]  = z / fmaxf(fabsf(z), 1e-12f);
        g_c[gid]  = clipf(accs * (1.f / (float)S_), 0.f, 1.f);
    }

    // ---- last-block-done: the final block runs sort + bucket ----
    __threadfence();
    if (tid == 0) {
        int old = atomicAdd(&g_done, 1);
        sdone = (old == (int)gridDim.x - 1) ? 1 : 0;
        if (sdone) g_done = 0;                 // reset for next graph replay
    }
    __syncthreads();
    if (!sdone) return;

    // ===== sort stage =====
    __shared__ float skey[N_];
    __shared__ int   sval[N_];
    __shared__ float ssw[N_], ssb[N_], sss[N_];   // by swizzled slot

    float tkey = 3.0f;
    if (tid < NM1_) {
        float w = w_diff[tid], bb = b_diff[tid];
        tkey = 2.0f;
        if (w > 0.f && (w + bb) > 1.f)        tkey = (1.f - bb) / w;
        else if (w < 0.f && (w + bb) < -1.f)  tkey = (-1.f - bb) / w;
    }
    skey[tid] = tkey;
    sval[tid] = tid;
    __syncthreads();

    for (int ksz = 2; ksz <= N_; ksz <<= 1) {
        for (int jsz = ksz >> 1; jsz > 0; jsz >>= 1) {
            int ixj = tid ^ jsz;
            if (ixj > tid) {
                bool up = ((tid & ksz) == 0);
                float a = skey[tid], c = skey[ixj];
                bool sw = up ? (a > c) : (a < c);
                if (sw) {
                    skey[tid] = c; skey[ixj] = a;
                    int tmp = sval[tid]; sval[tid] = sval[ixj]; sval[ixj] = tmp;
                }
            }
            __syncthreads();
        }
    }

    int n = sval[tid];
    float key = skey[tid];
    int slot = ((tid & 15) << 5) | (tid >> 4);
    if (n < NM1_) {
        float w = w_diff[n], bb = b_diff[n];
        ssw[slot] = w;
        ssb[slot] = bb;
        sss[slot] = (key >= 2.0f) ? 0.f : (w > 0.f ? 1.f : -1.f);
        g_perm[slot] = n + 1;
    } else {
        ssw[slot] = 0.f; ssb[slot] = 0.f; sss[slot] = 0.f;
        g_perm[slot] = 0;
    }

    if (tid == 0 && out_size > MEANDT_OFF) {
        float d0 = clipf(dt[0], 0.f, 1.f);
        float d1 = clipf(dt[1], 0.f, 1.f);
        out[MEANDT_OFF] = 0.5f * (d0 + d1);
    }

    // ===== bucket stage (kidx + parallel scan + rank + scatter) =====
    __shared__ int bs1[N_];
    __shared__ int bs2[N_];
    __shared__ int posA[N_];
    __shared__ int rnkS[N_];

    bs1[tid] = 0;
    __syncthreads();

    int kx[BS_ / 512];
    #pragma unroll
    for (int q = 0; q < BS_ / 512; q++) {
        int sid = q * 512 + tid;
        float c = g_c[sid];
        int lo = 0, hi = N_;
        while (lo < hi) {
            int mid = (lo + hi) >> 1;
            if (skey[mid] <= c) lo = mid + 1; else hi = mid;
        }
        kx[q] = lo;                  // provably <= 511 (sentinel keys 2.0/3.0 > 1 >= c)
        atomicAdd(&bs1[lo], 1);
    }
    __syncthreads();

    int myc = bs1[tid];
    int myf = (myc > 0) ? 1 : 0;
    bs2[tid] = myf;
    __syncthreads();

    for (int off = 1; off < N_; off <<= 1) {
        int a = 0, bb2 = 0;
        if (tid >= off) { a = bs1[tid - off]; bb2 = bs2[tid - off]; }
        __syncthreads();
        bs1[tid] += a; bs2[tid] += bb2;
        __syncthreads();
    }

    posA[tid] = bs1[tid] - myc;
    int r = myf ? (bs2[tid] - 1) : -1;
    rnkS[tid] = r;
    g_meta4[slot] = make_float4(ssw[slot], ssb[slot], sss[slot], __int_as_float(r));
    __syncthreads();

    #pragma unroll
    for (int q = 0; q < BS_ / 512; q++) {
        int sid = q * 512 + tid;
        int p = atomicAdd(&posA[kx[q]], 1);
        g_list[p] = sid;
        g_krank[sid] = rnkS[kx[q]];
    }
}

// ----------------------------- K2: tables from w_out rows (gather form) --------------------------
// One warp per token t. Lane l owns sorted positions j = l*16 + i; slot m = i*32 + l.
// D table holds the FINAL D (= D' + totc + b_out), so k_logits needs no E.
__global__ void __launch_bounds__(256) k_tables(const float* __restrict__ w_out,
                                                const float* __restrict__ b_out) {
    __shared__ float4 smeta[N_];          // 8 KB
    __shared__ int    sperm[N_];          // 2 KB
    __shared__ float  srow[WPB_T][N_];    // 16 KB

    int tid = threadIdx.x;
    for (int j = tid; j < N_; j += 256) {
        smeta[j] = g_meta4[j];
        sperm[j] = g_perm[j];
    }

    int wid  = tid >> 5;
    int lane = tid & 31;
    int t = blockIdx.x * WPB_T + wid;
    bool tv = (t < V_);

    if (tv) {
        const float4* rp = (const float4*)(w_out + (size_t)t * N_);
        float4* sp = (float4*)srow[wid];
        #pragma unroll
        for (int q = 0; q < 4; q++) sp[q * 32 + lane] = rp[q * 32 + lane];
    }
    __syncthreads();
    if (!tv) return;

    const float* row = srow[wid];
    float bo = b_out[t];

    // pass 1: per-lane suffix totals over its 16 positions
    float ta = 0.f, tb = 0.f, tc = 0.f;
    #pragma unroll
    for (int i = 15; i >= 0; i--) {
        int m = i * 32 + lane;
        float  w  = row[sperm[m]];
        float4 md = smeta[m];
        ta = fmaf(w, md.x, ta);
        tb = fmaf(w, md.y, tb);
        tc = fmaf(w, md.z, tc);
    }

    // inclusive suffix scan across lanes (lane l gets sum over lanes >= l)
    float ia = ta, ib = tb, ic = tc;
    #pragma unroll
    for (int off = 1; off < 32; off <<= 1) {
        float xa = __shfl_down_sync(0xffffffffu, ia, off);
        float xb = __shfl_down_sync(0xffffffffu, ib, off);
        float xc = __shfl_down_sync(0xffffffffu, ic, off);
        if (lane + off < 32) { ia += xa; ib += xb; ic += xc; }
    }
    float ba = ia - ta;
    float bb = ib - tb;
    float bc = ic - tc;
    float totc = __shfl_sync(0xffffffffu, ic, 0);
    float dadd = totc + bo;

    // pass 2: walk down, emit at used ranks (final D)
    float aa = ba, ab = bb, ac = bc;
    #pragma unroll
    for (int i = 15; i >= 0; i--) {
        int m = i * 32 + lane;
        float  w  = row[sperm[m]];
        float4 md = smeta[m];
        aa = fmaf(w, md.x, aa);
        ab = fmaf(w, md.y, ab);
        ac = fmaf(w, md.z, ac);
        int rk = __float_as_int(md.w);
        if (rk >= 0) {
            g_A[(size_t)rk * VP_ + t] = aa;
            g_D[(size_t)rk * VP_ + t] = ab - ac + dadd;
        }
    }

    if (lane == 0) g_W0[t] = row[0];
}

// ----------------------------- K3: logits (4 tok/thread, STG.128 mod-4-aligned) ------------------
// Thread t0 (multiple of 4) writes tokens t0+par .. t0+par+3 where par = (-sid*V) mod 4,
// making every store 16B-aligned. Tokens t0..t0+par-1 are covered by the previous thread,
// EXCEPT at the global left edge, which the t0==0 thread patches (up to 3 scalar stores).
__global__ void __launch_bounds__(512) k_logits(float* __restrict__ out) {
    __shared__ float4 sm[CH2_];   // (r, c, base-as-int-bits, rank-as-int-bits)

    int tid = threadIdx.x;
    if (tid < CH2_) {
        int sid = g_list[blockIdx.y * CH2_ + tid];
        sm[tid] = make_float4(g_r[sid], g_c[sid],
                              __int_as_float(sid * V_),
                              __int_as_float(g_krank[sid]));
    }
    __syncthreads();

    int t0 = blockIdx.x * 2048 + tid * 4;       // multiple of 4
    if (t0 >= V_) return;
    bool full  = (t0 + 6 < V_);                 // all possible stored tokens valid
    bool left0 = (t0 == 0);

    float w0[8];
    {
        float4 wa = *(const float4*)(g_W0 + t0);
        float4 wb = *(const float4*)(g_W0 + t0 + 4);
        w0[0] = wa.x; w0[1] = wa.y; w0[2] = wa.z; w0[3] = wa.w;
        w0[4] = wb.x; w0[5] = wb.y; w0[6] = wb.z; w0[7] = wb.w;
    }

    int kcur = -1;
    float A[8], D[8];
    #pragma unroll
    for (int j = 0; j < 8; j++) { A[j] = 0.f; D[j] = 0.f; }

    for (int p = 0; p < CH2_; p++) {
        float4 md = sm[p];
        int rk = __float_as_int(md.w);
        if (rk != kcur) {
            const float* ap = g_A + (size_t)rk * VP_ + t0;
            const float* dp = g_D + (size_t)rk * VP_ + t0;
            float4 a0 = *(const float4*)ap;
            float4 a1 = *(const float4*)(ap + 4);
            float4 d0 = *(const float4*)dp;
            float4 d1 = *(const float4*)(dp + 4);
            A[0] = a0.x; A[1] = a0.y; A[2] = a0.z; A[3] = a0.w;
            A[4] = a1.x; A[5] = a1.y; A[6] = a1.z; A[7] = a1.w;
            D[0] = d0.x; D[1] = d0.y; D[2] = d0.z; D[3] = d0.w;
            D[4] = d1.x; D[5] = d1.y; D[6] = d1.z; D[7] = d1.w;
            kcur = rk;
        }
        float r = md.x, c = md.y;
        int base = __float_as_int(md.z);
        int par  = (-base) & 3;              // store alignment shift (uniform per warp)

        float x0, x1, x2, x3;
        switch (par) {
        case 0:
            x0 = fmaf(r, w0[0], fmaf(c, A[0], D[0]));
            x1 = fmaf(r, w0[1], fmaf(c, A[1], D[1]));
            x2 = fmaf(r, w0[2], fmaf(c, A[2], D[2]));
            x3 = fmaf(r, w0[3], fmaf(c, A[3], D[3]));
            break;
        case 1:
            x0 = fmaf(r, w0[1], fmaf(c, A[1], D[1]));
            x1 = fmaf(r, w0[2], fmaf(c, A[2], D[2]));
            x2 = fmaf(r, w0[3], fmaf(c, A[3], D[3]));
            x3 = fmaf(r, w0[4], fmaf(c, A[4], D[4]));
            break;
        case 2:
            x0 = fmaf(r, w0[2], fmaf(c, A[2], D[2]));
            x1 = fmaf(r, w0[3], fmaf(c, A[3], D[3]));
            x2 = fmaf(r, w0[4], fmaf(c, A[4], D[4]));
            x3 = fmaf(r, w0[5], fmaf(c, A[5], D[5]));
            break;
        default:
            x0 = fmaf(r, w0[3], fmaf(c, A[3], D[3]));
            x1 = fmaf(r, w0[4], fmaf(c, A[4], D[4]));
            x2 = fmaf(r, w0[5], fmaf(c, A[5], D[5]));
            x3 = fmaf(r, w0[6], fmaf(c, A[6], D[6]));
            break;
        }
        x0 = fminf(fmaxf(x0, -2.f), 2.f);
        x1 = fminf(fmaxf(x1, -2.f), 2.f);
        x2 = fminf(fmaxf(x2, -2.f), 2.f);
        x3 = fminf(fmaxf(x3, -2.f), 2.f);

        float* addr = out + (size_t)(unsigned)base + (t0 + par);
        if (full) {
            __stcs((float4*)addr, make_float4(x0, x1, x2, x3));
        } else {
            int ts = t0 + par;
            if (ts     < V_) __stcs(addr,     x0);
            if (ts + 1 < V_) __stcs(addr + 1, x1);
            if (ts + 2 < V_) __stcs(addr + 2, x2);
            if (ts + 3 < V_) __stcs(addr + 3, x3);
        }
        // left-edge patch: tokens 0..par-1 have no predecessor thread
        if (left0 && par) {
            #pragma unroll
            for (int j = 0; j < 3; j++) {
                if (j < par) {
                    float xz = fmaf(r, w0[j], fmaf(c, A[j], D[j]));
                    xz = fminf(fmaxf(xz, -2.f), 2.f);
                    __stcs(out + (size_t)(unsigned)base + j, xz);
                }
            }
        }
    }
}

// ----------------------------- launch -----------------------------
extern "C" void kernel_launch(void* const* d_in, const int* in_sizes, int n_in,
                              void* d_out, int out_size) {
    const int*   x      = (const int*)  d_in[0];
    const float* dt     = (const float*)d_in[1];
    const float* r0     = (const float*)d_in[2];
    const float* w_diff = (const float*)d_in[3];
    const float* b_diff = (const float*)d_in[4];
    const float* w_out  = (const float*)d_in[5];
    const float* b_out  = (const float*)d_in[6];
    float* out = (float*)d_out;
    size_t osz = (size_t)out_size;

    int write_score = (osz >= SCORE_OFF + (size_t)BS_ * S_) ? 1 : 0;

    k_step1<<<BS_, 512>>>(x, dt, r0);
    k_step2<<<BS_, 512>>>(dt, w_diff, b_diff, out, write_score, osz);
    k_tables<<<(V_ + WPB_T - 1) / WPB_T, 256>>>(w_out, b_out);

    dim3 lg((V_ + 2047) / 2048, NZ2_);
    k_logits<<<lg, 512>>>(out);
}